// round 8
// baseline (speedup 1.0000x reference)
#include <cuda_runtime.h>
#include <cuda_bf16.h>

#define NN   512
#define NCH  20
#define H1   128
#define NB   32
#define NC   16
#define NJH  4          // j-range splits in k2
#define JR   (NN / NJH) // 128 j-rows per CTA
#define K2_CTAS (NB * 2 * NJH)   // 256
#define LOG2E 1.4426950408889634f

// Scratch — transposed layouts so combine loads are coalesced
__device__ float g_h[NCH * NN];              // hidden features, [c][i]
__device__ float g_M[NB * NN * NC];          // M*log2e, [b][i][c]
__device__ float g_opart[NJH * NB * NN];     // partials, [jh][b][i]
__device__ unsigned int g_count;             // last-CTA counter (reset by k1)

// Packed fp32x2 FMA — native FFMA2 on sm_103a
#define FMA2(d, a, b, c) \
    asm("fma.rn.f32x2 %0, %1, %2, %3;" : "=l"(d) : "l"(a), "l"(b), "l"(c))

// ---------------------------------------------------------------------------
// K1: MLP + projection. 64 CTAs x 256 threads, 8 rows per CTA.
// ALL global weight reads hoisted to entry (one overlapped L2 round-trip).
// ---------------------------------------------------------------------------
__global__ void __launch_bounds__(256) k1_mlp_proj(
    const float* __restrict__ x,  const float* __restrict__ W1,
    const float* __restrict__ b1, const float* __restrict__ W2,
    const float* __restrict__ b2, const float* __restrict__ T)
{
    const int i0 = blockIdx.x * 8;
    const int t  = threadIdx.x;

    if (blockIdx.x == 0 && t == 0) g_count = 0;   // reset fusion counter

    __shared__ float xs[8][NCH];
    __shared__ float h1s[8][H1];
    __shared__ float hs[8][NCH];
    __shared__ float W2s[H1 * NCH];   // 10 KB

    // ---- prefetch everything global, all independent, one latency wait ----
    const int c128 = t & 127;
    float w1c[NCH], tc0[NCH], tc1[NCH];
#pragma unroll
    for (int k = 0; k < NCH; ++k) {
        w1c[k] = W1[k * H1 + c128];
        tc0[k] = T[k * NN + t];
        tc1[k] = T[k * NN + t + 256];
    }
    {
        const float4* src = reinterpret_cast<const float4*>(W2);
        float4*       dst = reinterpret_cast<float4*>(W2s);
#pragma unroll
        for (int k = t; k < H1 * NCH / 4; k += 256) dst[k] = src[k];
    }
    if (t < 8 * NCH) xs[t / NCH][t % NCH] = x[i0 * NCH + t];
    const float b1c = b1[c128];
    __syncthreads();

    // fc1 + relu: thread handles column c for 4 rows
    {
        const int r0 = (t >> 7) * 4;
        float a0 = b1c, a1 = a0, a2 = a0, a3 = a0;
#pragma unroll
        for (int k = 0; k < NCH; ++k) {
            a0 = fmaf(xs[r0 + 0][k], w1c[k], a0);
            a1 = fmaf(xs[r0 + 1][k], w1c[k], a1);
            a2 = fmaf(xs[r0 + 2][k], w1c[k], a2);
            a3 = fmaf(xs[r0 + 3][k], w1c[k], a3);
        }
        h1s[r0 + 0][c128] = fmaxf(a0, 0.f);
        h1s[r0 + 1][c128] = fmaxf(a1, 0.f);
        h1s[r0 + 2][c128] = fmaxf(a2, 0.f);
        h1s[r0 + 3][c128] = fmaxf(a3, 0.f);
    }
    __syncthreads();

    // fc2 + relu: 160 outputs (r, c), weights from smem
    if (t < 8 * NCH) {
        const int r = t / NCH, c = t % NCH;
        float a0 = b2[c], a1 = 0.f, a2 = 0.f, a3 = 0.f;
#pragma unroll 8
        for (int k = 0; k < H1; k += 4) {
            a0 = fmaf(h1s[r][k + 0], W2s[(k + 0) * NCH + c], a0);
            a1 = fmaf(h1s[r][k + 1], W2s[(k + 1) * NCH + c], a1);
            a2 = fmaf(h1s[r][k + 2], W2s[(k + 2) * NCH + c], a2);
            a3 = fmaf(h1s[r][k + 3], W2s[(k + 3) * NCH + c], a3);
        }
        float a = fmaxf((a0 + a1) + (a2 + a3), 0.f);
        hs[r][c] = a;
        g_h[c * NN + (i0 + r)] = a;   // transposed write
    }
    __syncthreads();

    // proj: M = (h @ T) * log2e, layout [b][i][c]; cols t and t+256
#pragma unroll
    for (int g2 = 0; g2 < 2; ++g2) {
        const int col = t + g2 * 256;
        const float* tc = (g2 == 0) ? tc0 : tc1;
        const int b = col >> 4, cc = col & 15;
#pragma unroll
        for (int r = 0; r < 8; ++r) {
            float m = 0.f;
#pragma unroll
            for (int k = 0; k < NCH; ++k) m = fmaf(hs[r][k], tc[k], m);
            g_M[(b * NN + (i0 + r)) * NC + cc] = m * LOG2E;
        }
    }
}

// ---------------------------------------------------------------------------
// K2: pairwise L1 + exp2 (FFMA2 + parallel LOP3 abs), with k3 FUSED into the
// last CTA to finish.  grid = (32 b, 2 i-chunks, 4 j-ranges) = 256 CTAs x 256.
// ---------------------------------------------------------------------------
__global__ void __launch_bounds__(256) k2_pairwise(
    const float* __restrict__ W3, const float* __restrict__ b3,
    float* __restrict__ out)
{
    const int b  = blockIdx.x;
    const int ic = blockIdx.y;
    const int jh = blockIdx.z;
    const int t  = threadIdx.x;

    __shared__ float Mb[JR * NC];   // 8 KB (reused as reduce buffer in tail)
    __shared__ unsigned int sLast;

    {   // stage j-range (coalesced float4)
        const float4* src = reinterpret_cast<const float4*>(g_M + (b * NN + jh * JR) * NC);
        float4*       dst = reinterpret_cast<float4*>(Mb);
#pragma unroll
        for (int k = t; k < JR * NC / 4; k += 256) dst[k] = src[k];
    }
    __syncthreads();

    const int i = ic * 256 + t;
    unsigned long long mi[8];
    {
        const ulonglong2* gm = reinterpret_cast<const ulonglong2*>(g_M + (b * NN + i) * NC);
#pragma unroll
        for (int k = 0; k < 4; ++k) { ulonglong2 v = gm[k]; mi[2 * k] = v.x; mi[2 * k + 1] = v.y; }
    }

    const unsigned long long NEG1 = 0xBF800000BF800000ULL;  // (-1,-1)
    const unsigned long long ONE  = 0x3F8000003F800000ULL;  // ( 1, 1)
    const unsigned long long ABS2 = 0x7fffffff7fffffffULL;

    float oacc = 0.f;
#pragma unroll 2
    for (int j = 0; j < JR; ++j) {
        const ulonglong2* mj = reinterpret_cast<const ulonglong2*>(Mb + j * NC);
        unsigned long long a[8];
#pragma unroll
        for (int k = 0; k < 4; ++k) {
            ulonglong2 v = mj[k];
            unsigned long long t0, t1;
            FMA2(t0, v.x, NEG1, mi[2 * k]);        // mi - mj   (packed)
            FMA2(t1, v.y, NEG1, mi[2 * k + 1]);
            a[2 * k]     = t0 & ABS2;              // |.| on alu pipe
            a[2 * k + 1] = t1 & ABS2;
        }
        unsigned long long s0, s1, s2, s3;
        FMA2(s0, a[0], ONE, a[1]);  FMA2(s1, a[2], ONE, a[3]);
        FMA2(s2, a[4], ONE, a[5]);  FMA2(s3, a[6], ONE, a[7]);
        FMA2(s0, s0, ONE, s1);      FMA2(s2, s2, ONE, s3);
        FMA2(s0, s0, ONE, s2);
        float lo, hi;
        asm("mov.b64 {%0,%1}, %2;" : "=f"(lo), "=f"(hi) : "l"(s0));
        float nd = -lo - hi;                       // -(d*log2e), M prescaled
        float e;
        asm("ex2.approx.ftz.f32 %0, %1;" : "=f"(e) : "f"(nd));
        oacc += e;
    }
    g_opart[(jh * NB + b) * NN + i] = oacc;        // transposed, coalesced

    // ---- fused k3: last CTA to arrive does the head -----------------------
    __threadfence();
    if (t == 0) {
        unsigned int old = atomicAdd(&g_count, 1u);
        sLast = (old == K2_CTAS - 1) ? 1u : 0u;
    }
    __syncthreads();
    if (!sLast) return;

    // this CTA: 256 threads, rows t and t+256
    const int iA = t, iB = t + 256;
    float orA[NB], orB[NB];
    float sA = 0.f, sB = 0.f;
#pragma unroll
    for (int bb = 0; bb < NB; ++bb) {
        float vA = 0.f, vB = 0.f;
#pragma unroll
        for (int q = 0; q < NJH; ++q) {
            vA += g_opart[(q * NB + bb) * NN + iA];
            vB += g_opart[(q * NB + bb) * NN + iB];
        }
        orA[bb] = vA; orB[bb] = vB;
        sA += vA;     sB += vB;
    }
    float* red = Mb;                 // reuse smem
    red[t] = sA + sB;
    __syncthreads();
#pragma unroll
    for (int st = 128; st > 0; st >>= 1) {
        if (t < st) red[t] += red[t + st];
        __syncthreads();
    }
    const float mean = red[0] * (1.0f / (float)(NN * NB));

    float accA = b3[0], accB = b3[0];
#pragma unroll
    for (int c = 0; c < NCH; ++c) {
        accA = fmaf(g_h[c * NN + iA], W3[c], accA);
        accB = fmaf(g_h[c * NN + iB], W3[c], accB);
    }
#pragma unroll
    for (int bb = 0; bb < NB; ++bb) {
        accA = fmaf(orA[bb] - mean, W3[NCH + bb], accA);
        accB = fmaf(orB[bb] - mean, W3[NCH + bb], accB);
    }
    out[iA] = 1.0f / (1.0f + __expf(-accA));
    out[iB] = 1.0f / (1.0f + __expf(-accB));
}

// ---------------------------------------------------------------------------
extern "C" void kernel_launch(void* const* d_in, const int* in_sizes, int n_in,
                              void* d_out, int out_size)
{
    const float* x  = (const float*)d_in[0];
    const float* W1 = (const float*)d_in[1];
    const float* b1 = (const float*)d_in[2];
    const float* W2 = (const float*)d_in[3];
    const float* b2 = (const float*)d_in[4];
    const float* T  = (const float*)d_in[5];
    const float* W3 = (const float*)d_in[6];
    const float* b3 = (const float*)d_in[7];
    float* out = (float*)d_out;

    k1_mlp_proj<<<64, 256>>>(x, W1, b1, W2, b2, T);
    dim3 g2(NB, 2, NJH);
    k2_pairwise<<<g2, 256>>>(W3, b3, out);
}

// round 11
// speedup vs baseline: 1.1465x; 1.1465x over previous
#include <cuda_runtime.h>
#include <cuda_bf16.h>

#define NN   512
#define NCH  20
#define H1   128
#define NB   32
#define NC   16
#define NKR  4            // k-range splits in k2
#define LOG2E 1.4426950408889634f

// Scratch — transposed layouts so combine loads are coalesced
__device__ float g_h[NCH * NN];              // hidden features, [c][i]
__device__ float g_M[NB * NN * NC];          // M*log2e, [b][i][c]
__device__ float g_opart[NKR * NB * NN];     // partials, [kr][b][i]

// ---------------------------------------------------------------------------
// K1: MLP + projection. 64 CTAs x 256 threads, 8 rows per CTA.
// All global weight reads hoisted to entry (one overlapped L2 round-trip).
// ---------------------------------------------------------------------------
__global__ void __launch_bounds__(256) k1_mlp_proj(
    const float* __restrict__ x,  const float* __restrict__ W1,
    const float* __restrict__ b1, const float* __restrict__ W2,
    const float* __restrict__ b2, const float* __restrict__ T)
{
    const int i0 = blockIdx.x * 8;
    const int t  = threadIdx.x;

    __shared__ float xs[8][NCH];
    __shared__ float h1s[8][H1];
    __shared__ float hs[8][NCH];
    __shared__ float W2s[H1 * NCH];   // 10 KB

    // ---- prefetch everything global, all independent ----
    const int c128 = t & 127;
    float w1c[NCH], tc0[NCH], tc1[NCH];
#pragma unroll
    for (int k = 0; k < NCH; ++k) {
        w1c[k] = W1[k * H1 + c128];
        tc0[k] = T[k * NN + t];
        tc1[k] = T[k * NN + t + 256];
    }
    {
        const float4* src = reinterpret_cast<const float4*>(W2);
        float4*       dst = reinterpret_cast<float4*>(W2s);
#pragma unroll
        for (int k = t; k < H1 * NCH / 4; k += 256) dst[k] = src[k];
    }
    if (t < 8 * NCH) xs[t / NCH][t % NCH] = x[i0 * NCH + t];
    const float b1c = b1[c128];
    __syncthreads();

    // fc1 + relu
    {
        const int r0 = (t >> 7) * 4;
        float a0 = b1c, a1 = a0, a2 = a0, a3 = a0;
#pragma unroll
        for (int k = 0; k < NCH; ++k) {
            a0 = fmaf(xs[r0 + 0][k], w1c[k], a0);
            a1 = fmaf(xs[r0 + 1][k], w1c[k], a1);
            a2 = fmaf(xs[r0 + 2][k], w1c[k], a2);
            a3 = fmaf(xs[r0 + 3][k], w1c[k], a3);
        }
        h1s[r0 + 0][c128] = fmaxf(a0, 0.f);
        h1s[r0 + 1][c128] = fmaxf(a1, 0.f);
        h1s[r0 + 2][c128] = fmaxf(a2, 0.f);
        h1s[r0 + 3][c128] = fmaxf(a3, 0.f);
    }
    __syncthreads();

    // fc2 + relu
    if (t < 8 * NCH) {
        const int r = t / NCH, c = t % NCH;
        float a0 = b2[c], a1 = 0.f, a2 = 0.f, a3 = 0.f;
#pragma unroll 8
        for (int k = 0; k < H1; k += 4) {
            a0 = fmaf(h1s[r][k + 0], W2s[(k + 0) * NCH + c], a0);
            a1 = fmaf(h1s[r][k + 1], W2s[(k + 1) * NCH + c], a1);
            a2 = fmaf(h1s[r][k + 2], W2s[(k + 2) * NCH + c], a2);
            a3 = fmaf(h1s[r][k + 3], W2s[(k + 3) * NCH + c], a3);
        }
        float a = fmaxf((a0 + a1) + (a2 + a3), 0.f);
        hs[r][c] = a;
        g_h[c * NN + (i0 + r)] = a;   // transposed write
    }
    __syncthreads();

    // proj: M = (h @ T) * log2e, layout [b][i][c]
#pragma unroll
    for (int g2 = 0; g2 < 2; ++g2) {
        const int col = t + g2 * 256;
        const float* tc = (g2 == 0) ? tc0 : tc1;
        const int b = col >> 4, cc = col & 15;
#pragma unroll
        for (int r = 0; r < 8; ++r) {
            float m = 0.f;
#pragma unroll
            for (int k = 0; k < NCH; ++k) m = fmaf(hs[r][k], tc[k], m);
            g_M[(b * NN + (i0 + r)) * NC + cc] = m * LOG2E;
        }
    }
}

// ---------------------------------------------------------------------------
// K2: symmetric pairwise L1 + exp2 — each unordered pair computed ONCE.
// Thread i handles pair (i, i+k) for k in its range; the exp value feeds
// o_i directly and o_{i+k} via a shared-memory exchange (batch of 4 k's,
// two bars per batch).  k=256 is direct-only (pair computed by both ends).
// grid = (32 b, 4 k-ranges) = 128 CTAs x 512 threads.
// ---------------------------------------------------------------------------
__global__ void __launch_bounds__(512) k2_pairwise()
{
    const int b  = blockIdx.x;
    const int kr = blockIdx.y;
    const int i  = threadIdx.x;

    __shared__ float Ms[NN][17];   // 34816 B, padded: skewed LDS conflict-free
    __shared__ float sv[NN][5];    // 10240 B, padded exchange buffer

    // stage block b (512 x 16 floats) into padded smem
    {
        const float4* src = reinterpret_cast<const float4*>(g_M + b * NN * NC);
#pragma unroll
        for (int u = 0; u < 4; ++u) {
            const int idx = i + u * 512;        // float4 index, 2048 total
            const float4 v = src[idx];
            const int row = idx >> 2;
            const int c4  = (idx & 3) * 4;
            Ms[row][c4 + 0] = v.x; Ms[row][c4 + 1] = v.y;
            Ms[row][c4 + 2] = v.z; Ms[row][c4 + 3] = v.w;
        }
    }
    __syncthreads();

    float mi[NC];
#pragma unroll
    for (int c = 0; c < NC; ++c) mi[c] = Ms[i][c];

    float oacc = 0.f;
    const int kbase = kr * 64;

#pragma unroll 1
    for (int kb = 0; kb < 16; ++kb) {
#pragma unroll
        for (int q = 0; q < 4; ++q) {
            const int k = kbase + kb * 4 + q + 1;
            const int j = (i + k) & (NN - 1);
            const float* mj = Ms[j];
            // d = sum_c |mi - mj| : subs + folded-abs adds + tree
            float t0  = mi[0]  - mj[0],  t1  = mi[1]  - mj[1];
            float t2  = mi[2]  - mj[2],  t3  = mi[3]  - mj[3];
            float t4  = mi[4]  - mj[4],  t5  = mi[5]  - mj[5];
            float t6  = mi[6]  - mj[6],  t7  = mi[7]  - mj[7];
            float t8  = mi[8]  - mj[8],  t9  = mi[9]  - mj[9];
            float t10 = mi[10] - mj[10], t11 = mi[11] - mj[11];
            float t12 = mi[12] - mj[12], t13 = mi[13] - mj[13];
            float t14 = mi[14] - mj[14], t15 = mi[15] - mj[15];
            float a0 = fabsf(t0)  + fabsf(t1);
            float a1 = fabsf(t2)  + fabsf(t3);
            float a2 = fabsf(t4)  + fabsf(t5);
            float a3 = fabsf(t6)  + fabsf(t7);
            float a4 = fabsf(t8)  + fabsf(t9);
            float a5 = fabsf(t10) + fabsf(t11);
            float a6 = fabsf(t12) + fabsf(t13);
            float a7 = fabsf(t14) + fabsf(t15);
            float s0 = a0 + a1, s1 = a2 + a3, s2 = a4 + a5, s3 = a6 + a7;
            float u0 = s0 + s1, u1 = s2 + s3;
            float nd = -u0 - u1;                 // -(d*log2e), M prescaled
            float e;
            asm("ex2.approx.ftz.f32 %0, %1;" : "=f"(e) : "f"(nd));
            oacc += e;                           // direct term (j = i+k)
            sv[i][q] = e;
        }
        __syncthreads();
#pragma unroll
        for (int q = 0; q < 4; ++q) {
            const int k = kbase + kb * 4 + q + 1;
            if (k < 256)                         // k==256: direct only
                oacc += sv[(i - k) & (NN - 1)][q];   // cross term (j = i-k)
        }
        __syncthreads();
    }

    g_opart[(kr * NB + b) * NN + i] = oacc;      // coalesced
}

// ---------------------------------------------------------------------------
// K3: combine partials (+1 self term), deterministic mean, final head.
// ---------------------------------------------------------------------------
__global__ void __launch_bounds__(512) k3_head(
    const float* __restrict__ W3, const float* __restrict__ b3,
    float* __restrict__ out)
{
    const int i = threadIdx.x;
    __shared__ float red[NN];

    float orow[NB];
    float s = 0.0f;
#pragma unroll
    for (int b = 0; b < NB; ++b) {
        float v = 1.0f;                          // j == i self term
#pragma unroll
        for (int q = 0; q < NKR; ++q)
            v += g_opart[(q * NB + b) * NN + i];
        orow[b] = v;
        s += v;
    }
    red[i] = s;
    __syncthreads();

#pragma unroll
    for (int st = 256; st > 0; st >>= 1) {
        if (i < st) red[i] += red[i + st];
        __syncthreads();
    }
    const float mean = red[0] * (1.0f / (float)(NN * NB));

    float acc = b3[0];
#pragma unroll
    for (int c = 0; c < NCH; ++c)
        acc = fmaf(g_h[c * NN + i], W3[c], acc);
#pragma unroll
    for (int b = 0; b < NB; ++b)
        acc = fmaf(orow[b] - mean, W3[NCH + b], acc);

    out[i] = 1.0f / (1.0f + __expf(-acc));
}

// ---------------------------------------------------------------------------
extern "C" void kernel_launch(void* const* d_in, const int* in_sizes, int n_in,
                              void* d_out, int out_size)
{
    const float* x  = (const float*)d_in[0];
    const float* W1 = (const float*)d_in[1];
    const float* b1 = (const float*)d_in[2];
    const float* W2 = (const float*)d_in[3];
    const float* b2 = (const float*)d_in[4];
    const float* T  = (const float*)d_in[5];
    const float* W3 = (const float*)d_in[6];
    const float* b3 = (const float*)d_in[7];
    float* out = (float*)d_out;

    k1_mlp_proj<<<64, 256>>>(x, W1, b1, W2, b2, T);
    dim3 g2(NB, NKR);
    k2_pairwise<<<g2, 512>>>();
    k3_head<<<1, NN>>>(W3, b3, out);
}

// round 12
// speedup vs baseline: 1.2934x; 1.1281x over previous
#include <cuda_runtime.h>
#include <cuda_bf16.h>

#define NN   512
#define NCH  20
#define H1   128
#define NB   32
#define NC   16
#define NKR  4            // k-range splits in k2
#define LOG2E 1.4426950408889634f

// Scratch — transposed layouts so combine loads are coalesced
__device__ __align__(16) float g_h[NCH * NN];          // hidden, [c][i]
__device__ __align__(16) float g_M[NB * NN * NC];      // M*log2e, [b][i][c]
__device__ __align__(16) float g_opart[NKR * NB * NN]; // partials, [kr][b][i]

// ---------------------------------------------------------------------------
// K1: MLP + projection. 128 CTAs x 256 threads, 4 rows per CTA.
// Proj restructured: hs[r][*] loaded once per r into registers.
// ---------------------------------------------------------------------------
__global__ void __launch_bounds__(256) k1_mlp_proj(
    const float* __restrict__ x,  const float* __restrict__ W1,
    const float* __restrict__ b1, const float* __restrict__ W2,
    const float* __restrict__ b2, const float* __restrict__ T)
{
    const int i0 = blockIdx.x * 4;
    const int t  = threadIdx.x;

    __shared__ float xs[4][NCH];
    __shared__ float h1s[4][132];        // padded: conflict-free fc2 reads
    __shared__ float hs[4][NCH];
    __shared__ float W2s[H1 * NCH];      // 10 KB
    __shared__ float part[3][4 * NCH];   // fc2 k-slice partials

    // ---- prefetch everything global, all independent ----
    const int c128 = t & 127;
    float w1c[NCH], tc0[NCH], tc1[NCH];
#pragma unroll
    for (int k = 0; k < NCH; ++k) {
        w1c[k] = W1[k * H1 + c128];
        tc0[k] = T[k * NN + t];
        tc1[k] = T[k * NN + t + 256];
    }
    {
        const float4* src = reinterpret_cast<const float4*>(W2);
        float4*       dst = reinterpret_cast<float4*>(W2s);
#pragma unroll
        for (int k = t; k < H1 * NCH / 4; k += 256) dst[k] = src[k];
    }
    if (t < 4 * NCH) xs[t / NCH][t % NCH] = x[i0 * NCH + t];
    const float b1c = b1[c128];
    __syncthreads();

    // fc1 + relu: thread = (col c128, half) -> 2 rows each
    {
        const int r0 = (t >> 7) * 2;
        float a0 = b1c, a1 = a0;
#pragma unroll
        for (int k = 0; k < NCH; ++k) {
            a0 = fmaf(xs[r0 + 0][k], w1c[k], a0);
            a1 = fmaf(xs[r0 + 1][k], w1c[k], a1);
        }
        h1s[r0 + 0][c128] = fmaxf(a0, 0.f);
        h1s[r0 + 1][c128] = fmaxf(a1, 0.f);
    }
    __syncthreads();

    // fc2: 80 outputs x 3 k-slices = 240 threads
    if (t < 240) {
        const int q = t / 80, o = t % 80;
        const int r = o / NCH, c = o % NCH;
        const int k0 = q * 43, k1e = (q == 2) ? H1 : k0 + 43;
        float a = 0.f;
        for (int k = k0; k < k1e; ++k)
            a = fmaf(h1s[r][k], W2s[k * NCH + c], a);
        part[q][o] = a;
    }
    __syncthreads();
    if (t < 80) {
        const int r = t / NCH, c = t % NCH;
        float a = b2[c] + ((part[0][t] + part[1][t]) + part[2][t]);
        a = fmaxf(a, 0.f);
        hs[r][c] = a;
        g_h[c * NN + (i0 + r)] = a;      // transposed write
    }
    __syncthreads();

    // proj: per r, load hs[r][*] once -> 2 cols x 20 FMA
#pragma unroll
    for (int r = 0; r < 4; ++r) {
        float hr[NCH];
#pragma unroll
        for (int k = 0; k < NCH; ++k) hr[k] = hs[r][k];
        float m0 = 0.f, m1 = 0.f;
#pragma unroll
        for (int k = 0; k < NCH; ++k) {
            m0 = fmaf(hr[k], tc0[k], m0);
            m1 = fmaf(hr[k], tc1[k], m1);
        }
        const int colA = t, colB = t + 256;
        g_M[((colA >> 4) * NN + (i0 + r)) * NC + (colA & 15)] = m0 * LOG2E;
        g_M[((colB >> 4) * NN + (i0 + r)) * NC + (colB & 15)] = m1 * LOG2E;
    }
}

// ---------------------------------------------------------------------------
// K2: symmetric pairwise L1 + exp2, each unordered pair ONCE.
// Ms rows padded to 20 floats: LDS.128 x4 per pair, conflict-free.
// sv transposed [q][i]: stride-1 exchange, conflict-free.
// grid = (32 b, 4 k-ranges) = 128 CTAs x 512 threads.
// ---------------------------------------------------------------------------
__global__ void __launch_bounds__(512) k2_pairwise()
{
    const int b  = blockIdx.x;
    const int kr = blockIdx.y;
    const int i  = threadIdx.x;

    __shared__ float Ms[NN][20];   // 40960 B
    __shared__ float sv[4][NN];    //  8192 B  (total = 48 KB exactly)

    // mi from global (coalesced, overlaps staging)
    float4 mi0, mi1, mi2, mi3;
    {
        const float4* gm = reinterpret_cast<const float4*>(g_M + (b * NN + i) * NC);
        mi0 = gm[0]; mi1 = gm[1]; mi2 = gm[2]; mi3 = gm[3];
    }
    // stage block b into padded smem (LDG.128 + STS.128)
    {
        const float4* src = reinterpret_cast<const float4*>(g_M + b * NN * NC);
#pragma unroll
        for (int u = 0; u < 4; ++u) {
            const int idx = i + u * 512;        // float4 index
            const float4 v = src[idx];
            *reinterpret_cast<float4*>(&Ms[idx >> 2][(idx & 3) * 4]) = v;
        }
    }
    __syncthreads();

    float oacc = 0.f;
    const int kbase = kr * 64;

#pragma unroll 1
    for (int kb = 0; kb < 16; ++kb) {
#pragma unroll
        for (int q = 0; q < 4; ++q) {
            const int k = kbase + kb * 4 + q + 1;
            const int j = (i + k) & (NN - 1);
            const float4 a0 = *reinterpret_cast<const float4*>(&Ms[j][0]);
            const float4 a1 = *reinterpret_cast<const float4*>(&Ms[j][4]);
            const float4 a2 = *reinterpret_cast<const float4*>(&Ms[j][8]);
            const float4 a3 = *reinterpret_cast<const float4*>(&Ms[j][12]);
            float s0 = fabsf(mi0.x - a0.x) + fabsf(mi0.y - a0.y);
            float s1 = fabsf(mi0.z - a0.z) + fabsf(mi0.w - a0.w);
            float s2 = fabsf(mi1.x - a1.x) + fabsf(mi1.y - a1.y);
            float s3 = fabsf(mi1.z - a1.z) + fabsf(mi1.w - a1.w);
            float s4 = fabsf(mi2.x - a2.x) + fabsf(mi2.y - a2.y);
            float s5 = fabsf(mi2.z - a2.z) + fabsf(mi2.w - a2.w);
            float s6 = fabsf(mi3.x - a3.x) + fabsf(mi3.y - a3.y);
            float s7 = fabsf(mi3.z - a3.z) + fabsf(mi3.w - a3.w);
            float u0 = (s0 + s1) + (s2 + s3);
            float u1 = (s4 + s5) + (s6 + s7);
            float nd = -u0 - u1;               // -(d*log2e), M prescaled
            float e;
            asm("ex2.approx.ftz.f32 %0, %1;" : "=f"(e) : "f"(nd));
            oacc += e;                         // direct term (j = i+k)
            sv[q][i] = e;
        }
        __syncthreads();
#pragma unroll
        for (int q = 0; q < 4; ++q) {
            const int k = kbase + kb * 4 + q + 1;
            if (k < 256)                       // k==256: direct only
                oacc += sv[q][(i - k) & (NN - 1)];  // cross term (j = i-k)
        }
        __syncthreads();
    }

    g_opart[(kr * NB + b) * NN + i] = oacc;    // coalesced
}

// ---------------------------------------------------------------------------
// K3: combine partials (+1 self term), deterministic mean, final head.
// ---------------------------------------------------------------------------
__global__ void __launch_bounds__(512) k3_head(
    const float* __restrict__ W3, const float* __restrict__ b3,
    float* __restrict__ out)
{
    const int i = threadIdx.x;
    __shared__ float red[NN];

    float orow[NB];
    float s = 0.0f;
#pragma unroll
    for (int b = 0; b < NB; ++b) {
        float v = 1.0f;                        // j == i self term
#pragma unroll
        for (int q = 0; q < NKR; ++q)
            v += g_opart[(q * NB + b) * NN + i];
        orow[b] = v;
        s += v;
    }
    red[i] = s;
    __syncthreads();

#pragma unroll
    for (int st = 256; st > 0; st >>= 1) {
        if (i < st) red[i] += red[i + st];
        __syncthreads();
    }
    const float mean = red[0] * (1.0f / (float)(NN * NB));

    float acc = b3[0];
#pragma unroll
    for (int c = 0; c < NCH; ++c)
        acc = fmaf(g_h[c * NN + i], W3[c], acc);
#pragma unroll
    for (int b = 0; b < NB; ++b)
        acc = fmaf(orow[b] - mean, W3[NCH + b], acc);

    out[i] = 1.0f / (1.0f + __expf(-acc));
}

// ---------------------------------------------------------------------------
extern "C" void kernel_launch(void* const* d_in, const int* in_sizes, int n_in,
                              void* d_out, int out_size)
{
    const float* x  = (const float*)d_in[0];
    const float* W1 = (const float*)d_in[1];
    const float* b1 = (const float*)d_in[2];
    const float* W2 = (const float*)d_in[3];
    const float* b2 = (const float*)d_in[4];
    const float* T  = (const float*)d_in[5];
    const float* W3 = (const float*)d_in[6];
    const float* b3 = (const float*)d_in[7];
    float* out = (float*)d_out;

    k1_mlp_proj<<<128, 256>>>(x, W1, b1, W2, b2, T);
    dim3 g2(NB, NKR);
    k2_pairwise<<<g2, 512>>>();
    k3_head<<<1, NN>>>(W3, b3, out);
}

// round 13
// speedup vs baseline: 1.3101x; 1.0130x over previous
#include <cuda_runtime.h>
#include <cuda_bf16.h>

#define NN   512
#define NCH  20
#define H1   128
#define NB   32
#define NC   16
#define NKR  4            // k-range splits in k2
#define LOG2E 1.4426950408889634f

// Scratch — transposed layouts so combine loads are coalesced
__device__ __align__(16) float g_h[NCH * NN];          // hidden, [c][i]
__device__ __align__(16) float g_M[NB * NN * NC];      // M*log2e, [b][i][c]
__device__ __align__(16) float g_opart[NKR * NB * NN]; // partials, [kr][b][i]

// ---------------------------------------------------------------------------
// K1: MLP + projection. 128 CTAs x 256 threads, 4 rows per CTA.
// Proj restructured: hs[r][*] loaded once per r into registers.
// ---------------------------------------------------------------------------
__global__ void __launch_bounds__(256) k1_mlp_proj(
    const float* __restrict__ x,  const float* __restrict__ W1,
    const float* __restrict__ b1, const float* __restrict__ W2,
    const float* __restrict__ b2, const float* __restrict__ T)
{
    const int i0 = blockIdx.x * 4;
    const int t  = threadIdx.x;

    __shared__ float xs[4][NCH];
    __shared__ float h1s[4][132];        // padded: conflict-free fc2 reads
    __shared__ float hs[4][NCH];
    __shared__ float W2s[H1 * NCH];      // 10 KB
    __shared__ float part[3][4 * NCH];   // fc2 k-slice partials

    // ---- prefetch everything global, all independent ----
    const int c128 = t & 127;
    float w1c[NCH], tc0[NCH], tc1[NCH];
#pragma unroll
    for (int k = 0; k < NCH; ++k) {
        w1c[k] = W1[k * H1 + c128];
        tc0[k] = T[k * NN + t];
        tc1[k] = T[k * NN + t + 256];
    }
    {
        const float4* src = reinterpret_cast<const float4*>(W2);
        float4*       dst = reinterpret_cast<float4*>(W2s);
#pragma unroll
        for (int k = t; k < H1 * NCH / 4; k += 256) dst[k] = src[k];
    }
    if (t < 4 * NCH) xs[t / NCH][t % NCH] = x[i0 * NCH + t];
    const float b1c = b1[c128];
    __syncthreads();

    // fc1 + relu: thread = (col c128, half) -> 2 rows each
    {
        const int r0 = (t >> 7) * 2;
        float a0 = b1c, a1 = a0;
#pragma unroll
        for (int k = 0; k < NCH; ++k) {
            a0 = fmaf(xs[r0 + 0][k], w1c[k], a0);
            a1 = fmaf(xs[r0 + 1][k], w1c[k], a1);
        }
        h1s[r0 + 0][c128] = fmaxf(a0, 0.f);
        h1s[r0 + 1][c128] = fmaxf(a1, 0.f);
    }
    __syncthreads();

    // fc2: 80 outputs x 3 k-slices = 240 threads
    if (t < 240) {
        const int q = t / 80, o = t % 80;
        const int r = o / NCH, c = o % NCH;
        const int k0 = q * 43, k1e = (q == 2) ? H1 : k0 + 43;
        float a = 0.f;
        for (int k = k0; k < k1e; ++k)
            a = fmaf(h1s[r][k], W2s[k * NCH + c], a);
        part[q][o] = a;
    }
    __syncthreads();
    if (t < 80) {
        const int r = t / NCH, c = t % NCH;
        float a = b2[c] + ((part[0][t] + part[1][t]) + part[2][t]);
        a = fmaxf(a, 0.f);
        hs[r][c] = a;
        g_h[c * NN + (i0 + r)] = a;      // transposed write
    }
    __syncthreads();

    // proj: per r, load hs[r][*] once -> 2 cols x 20 FMA
#pragma unroll
    for (int r = 0; r < 4; ++r) {
        float hr[NCH];
#pragma unroll
        for (int k = 0; k < NCH; ++k) hr[k] = hs[r][k];
        float m0 = 0.f, m1 = 0.f;
#pragma unroll
        for (int k = 0; k < NCH; ++k) {
            m0 = fmaf(hr[k], tc0[k], m0);
            m1 = fmaf(hr[k], tc1[k], m1);
        }
        const int colA = t, colB = t + 256;
        g_M[((colA >> 4) * NN + (i0 + r)) * NC + (colA & 15)] = m0 * LOG2E;
        g_M[((colB >> 4) * NN + (i0 + r)) * NC + (colB & 15)] = m1 * LOG2E;
    }
}

// ---------------------------------------------------------------------------
// K2: symmetric pairwise L1 + exp2, each unordered pair ONCE.
// Ms rows padded to 20 floats: LDS.128 x4 per pair, conflict-free.
// sv transposed [q][i]: stride-1 exchange, conflict-free.
// grid = (32 b, 4 k-ranges) = 128 CTAs x 512 threads.
// ---------------------------------------------------------------------------
__global__ void __launch_bounds__(512) k2_pairwise()
{
    const int b  = blockIdx.x;
    const int kr = blockIdx.y;
    const int i  = threadIdx.x;

    __shared__ float Ms[NN][20];   // 40960 B
    __shared__ float sv[4][NN];    //  8192 B  (total = 48 KB exactly)

    // mi from global (coalesced, overlaps staging)
    float4 mi0, mi1, mi2, mi3;
    {
        const float4* gm = reinterpret_cast<const float4*>(g_M + (b * NN + i) * NC);
        mi0 = gm[0]; mi1 = gm[1]; mi2 = gm[2]; mi3 = gm[3];
    }
    // stage block b into padded smem (LDG.128 + STS.128)
    {
        const float4* src = reinterpret_cast<const float4*>(g_M + b * NN * NC);
#pragma unroll
        for (int u = 0; u < 4; ++u) {
            const int idx = i + u * 512;        // float4 index
            const float4 v = src[idx];
            *reinterpret_cast<float4*>(&Ms[idx >> 2][(idx & 3) * 4]) = v;
        }
    }
    __syncthreads();

    float oacc = 0.f;
    const int kbase = kr * 64;

#pragma unroll 1
    for (int kb = 0; kb < 16; ++kb) {
#pragma unroll
        for (int q = 0; q < 4; ++q) {
            const int k = kbase + kb * 4 + q + 1;
            const int j = (i + k) & (NN - 1);
            const float4 a0 = *reinterpret_cast<const float4*>(&Ms[j][0]);
            const float4 a1 = *reinterpret_cast<const float4*>(&Ms[j][4]);
            const float4 a2 = *reinterpret_cast<const float4*>(&Ms[j][8]);
            const float4 a3 = *reinterpret_cast<const float4*>(&Ms[j][12]);
            float s0 = fabsf(mi0.x - a0.x) + fabsf(mi0.y - a0.y);
            float s1 = fabsf(mi0.z - a0.z) + fabsf(mi0.w - a0.w);
            float s2 = fabsf(mi1.x - a1.x) + fabsf(mi1.y - a1.y);
            float s3 = fabsf(mi1.z - a1.z) + fabsf(mi1.w - a1.w);
            float s4 = fabsf(mi2.x - a2.x) + fabsf(mi2.y - a2.y);
            float s5 = fabsf(mi2.z - a2.z) + fabsf(mi2.w - a2.w);
            float s6 = fabsf(mi3.x - a3.x) + fabsf(mi3.y - a3.y);
            float s7 = fabsf(mi3.z - a3.z) + fabsf(mi3.w - a3.w);
            float u0 = (s0 + s1) + (s2 + s3);
            float u1 = (s4 + s5) + (s6 + s7);
            float nd = -u0 - u1;               // -(d*log2e), M prescaled
            float e;
            asm("ex2.approx.ftz.f32 %0, %1;" : "=f"(e) : "f"(nd));
            oacc += e;                         // direct term (j = i+k)
            sv[q][i] = e;
        }
        __syncthreads();
#pragma unroll
        for (int q = 0; q < 4; ++q) {
            const int k = kbase + kb * 4 + q + 1;
            if (k < 256)                       // k==256: direct only
                oacc += sv[q][(i - k) & (NN - 1)];  // cross term (j = i-k)
        }
        __syncthreads();
    }

    g_opart[(kr * NB + b) * NN + i] = oacc;    // coalesced
}

// ---------------------------------------------------------------------------
// K3: combine partials (+1 self term), deterministic mean, final head.
// ---------------------------------------------------------------------------
__global__ void __launch_bounds__(512) k3_head(
    const float* __restrict__ W3, const float* __restrict__ b3,
    float* __restrict__ out)
{
    const int i = threadIdx.x;
    __shared__ float red[NN];

    float orow[NB];
    float s = 0.0f;
#pragma unroll
    for (int b = 0; b < NB; ++b) {
        float v = 1.0f;                        // j == i self term
#pragma unroll
        for (int q = 0; q < NKR; ++q)
            v += g_opart[(q * NB + b) * NN + i];
        orow[b] = v;
        s += v;
    }
    red[i] = s;
    __syncthreads();

#pragma unroll
    for (int st = 256; st > 0; st >>= 1) {
        if (i < st) red[i] += red[i + st];
        __syncthreads();
    }
    const float mean = red[0] * (1.0f / (float)(NN * NB));

    float acc = b3[0];
#pragma unroll
    for (int c = 0; c < NCH; ++c)
        acc = fmaf(g_h[c * NN + i], W3[c], acc);
#pragma unroll
    for (int b = 0; b < NB; ++b)
        acc = fmaf(orow[b] - mean, W3[NCH + b], acc);

    out[i] = 1.0f / (1.0f + __expf(-acc));
}

// ---------------------------------------------------------------------------
extern "C" void kernel_launch(void* const* d_in, const int* in_sizes, int n_in,
                              void* d_out, int out_size)
{
    const float* x  = (const float*)d_in[0];
    const float* W1 = (const float*)d_in[1];
    const float* b1 = (const float*)d_in[2];
    const float* W2 = (const float*)d_in[3];
    const float* b2 = (const float*)d_in[4];
    const float* T  = (const float*)d_in[5];
    const float* W3 = (const float*)d_in[6];
    const float* b3 = (const float*)d_in[7];
    float* out = (float*)d_out;

    k1_mlp_proj<<<128, 256>>>(x, W1, b1, W2, b2, T);
    dim3 g2(NB, NKR);
    k2_pairwise<<<g2, 512>>>();
    k3_head<<<1, NN>>>(W3, b3, out);
}